// round 6
// baseline (speedup 1.0000x reference)
#include <cuda_runtime.h>

#define BGRAPH 64
#define HID    128
#define NCLS   10
#define NMLP   16      // blocks 0..15 run the MLP tail (4 graph rows each)
#define TPB    256
#define ELEMS_PER_BLOCK 2048   // 256 threads x 8 elements

// Persistent scratch (allocation-free rule: __device__ globals)
// sums:   [0,64) comp | [64,128) port c0 | [128,192) port c1 | [192,256) net
// counts: [256,320) comp | [320,384) port | [384,448) net
__device__ float g_acc[7 * BGRAPH];
__device__ int   g_ctr;    // pooling-done counter
__device__ int   g_ctr2;   // mlp g_acc-read-done counter

// ---------------------------------------------------------------------------
// run-accumulating pooling over 8 contiguous elements per thread.
// Sorted gids => ~1 run per thread => 2-3 fire-and-forget atomics per thread.
// ---------------------------------------------------------------------------
__device__ __forceinline__ void flush_sc(int bs, int bc, int gid, float acc, float cnt) {
    if (gid >= 0) {
        atomicAdd(&g_acc[bs + gid], acc);
        atomicAdd(&g_acc[bc + gid], cnt);
    }
}

__device__ __forceinline__ void pool_scalar(const float* __restrict__ f,
                                            const int* __restrict__ g,
                                            int n, int base, int bs, int bc) {
    const int t = threadIdx.x;
    int  cur = -1;
    float acc = 0.f, cnt = 0.f;

    int e0 = base + 4 * t;
    int e1 = base + 1024 + 4 * t;

    // hoist all loads (MLP)
    float4 v0, v1; int4 g0, g1;
    bool ok0 = (e0 + 4 <= n), ok1 = (e1 + 4 <= n);
    if (ok0) { v0 = *(const float4*)(f + e0); g0 = *(const int4*)(g + e0); }
    if (ok1) { v1 = *(const float4*)(f + e1); g1 = *(const int4*)(g + e1); }

#define PROC(GI, VV) do { \
        if ((GI) != cur) { flush_sc(bs, bc, cur, acc, cnt); cur = (GI); acc = (VV); cnt = 1.f; } \
        else { acc += (VV); cnt += 1.f; } } while (0)

    if (ok0) { PROC(g0.x, v0.x); PROC(g0.y, v0.y); PROC(g0.z, v0.z); PROC(g0.w, v0.w); }
    else {
        for (int j = 0; j < 4; j++) { int e = e0 + j; if (e < n) { int gi = g[e]; float vv = f[e]; PROC(gi, vv); } }
    }
    if (ok1) { PROC(g1.x, v1.x); PROC(g1.y, v1.y); PROC(g1.z, v1.z); PROC(g1.w, v1.w); }
    else {
        for (int j = 0; j < 4; j++) { int e = e1 + j; if (e < n) { int gi = g[e]; float vv = f[e]; PROC(gi, vv); } }
    }
#undef PROC
    flush_sc(bs, bc, cur, acc, cnt);
}

__device__ __forceinline__ void flush_port(int gid, float a0, float a1, float cnt) {
    if (gid >= 0) {
        atomicAdd(&g_acc[64  + gid], a0);
        atomicAdd(&g_acc[128 + gid], a1);
        atomicAdd(&g_acc[320 + gid], cnt);
    }
}

__device__ __forceinline__ void pool_port(const float* __restrict__ f,
                                          const int* __restrict__ g,
                                          int n, int base) {
    const int t = threadIdx.x;
    int  cur = -1;
    float a0 = 0.f, a1 = 0.f, cnt = 0.f;

    int e0 = base + 4 * t;
    int e1 = base + 1024 + 4 * t;

    float4 u0, w0, u1, w1; int4 g0, g1;
    bool ok0 = (e0 + 4 <= n), ok1 = (e1 + 4 <= n);
    if (ok0) {
        u0 = *(const float4*)(f + 2 * e0);
        w0 = *(const float4*)(f + 2 * e0 + 4);
        g0 = *(const int4*)(g + e0);
    }
    if (ok1) {
        u1 = *(const float4*)(f + 2 * e1);
        w1 = *(const float4*)(f + 2 * e1 + 4);
        g1 = *(const int4*)(g + e1);
    }

#define PROCP(GI, X, Y) do { \
        if ((GI) != cur) { flush_port(cur, a0, a1, cnt); cur = (GI); a0 = (X); a1 = (Y); cnt = 1.f; } \
        else { a0 += (X); a1 += (Y); cnt += 1.f; } } while (0)

    if (ok0) { PROCP(g0.x, u0.x, u0.y); PROCP(g0.y, u0.z, u0.w); PROCP(g0.z, w0.x, w0.y); PROCP(g0.w, w0.z, w0.w); }
    else {
        for (int j = 0; j < 4; j++) { int e = e0 + j; if (e < n) { int gi = g[e]; PROCP(gi, f[2*e], f[2*e+1]); } }
    }
    if (ok1) { PROCP(g1.x, u1.x, u1.y); PROCP(g1.y, u1.z, u1.w); PROCP(g1.z, w1.x, w1.y); PROCP(g1.w, w1.z, w1.w); }
    else {
        for (int j = 0; j < 4; j++) { int e = e1 + j; if (e < n) { int gi = g[e]; PROCP(gi, f[2*e], f[2*e+1]); } }
    }
#undef PROCP
    flush_port(cur, a0, a1, cnt);
}

// ---------------------------------------------------------------------------
// fused kernel
// ---------------------------------------------------------------------------
__global__ void __launch_bounds__(TPB)
k_fused(const float* __restrict__ hc, const float* __restrict__ hp,
        const float* __restrict__ hn,
        const int* __restrict__ gc, const int* __restrict__ gp,
        const int* __restrict__ gn,
        int nc, int np, int nn, int Bc, int Bp,
        const float* __restrict__ Wc1, const float* __restrict__ bc1,
        const float* __restrict__ Wc2, const float* __restrict__ bc2,
        const float* __restrict__ Wc3, const float* __restrict__ bc3,
        float* __restrict__ out) {
    const int t = threadIdx.x;
    const int b = blockIdx.x;

    // ===================== phase 1: pooling =====================
    if (b < Bc)            pool_scalar(hc, gc, nc, b * ELEMS_PER_BLOCK, 0, 256);
    else if (b < Bc + Bp)  pool_port  (hp, gp, np, (b - Bc) * ELEMS_PER_BLOCK);
    else                   pool_scalar(hn, gn, nn, (b - Bc - Bp) * ELEMS_PER_BLOCK, 192, 384);

    __syncthreads();
    if (t == 0) {
        __threadfence();
        atomicAdd(&g_ctr, 1);
    }
    if (b >= NMLP) return;                 // non-elected blocks retire immediately

    // ============== elected blocks (b < 16): prefetch weights to smem =======
    // NOTE: 16-byte alignment is mandatory on every array touched via float4
    // (shared arrays are only element-aligned by default — R5 trap).
    __shared__ __align__(16) float sW[32][HID];       // 16 KB Wc2 tile (float4 r/w)
    __shared__ __align__(16) float sWc1[4 * HID];     // 2 KB
    __shared__ __align__(16) float sWc3[HID * NCLS];  // 5 KB
    __shared__ __align__(16) float sb1[HID];
    __shared__ __align__(16) float sb2[HID];
    __shared__ __align__(16) float sb3[16];           // padded
    __shared__ __align__(16) float hg[4][4];
    __shared__ __align__(16) float h1s[4][HID];
    __shared__ __align__(16) float h2s[4][HID];
    __shared__ int s_r2;

    for (int i = t; i < 4 * HID; i += TPB) sWc1[i] = Wc1[i];
    for (int i = t; i < HID; i += TPB) { sb1[i] = bc1[i]; sb2[i] = bc2[i]; }
    for (int i = t; i < HID * NCLS; i += TPB) sWc3[i] = Wc3[i];
    if (t < NCLS) sb3[t] = bc3[t];

    // wait for all blocks' pooling (overlapped with the prefetch above)
    const int npool = gridDim.x;
    if (t == 0) {
        while (atomicAdd(&g_ctr, 0) < npool) __nanosleep(64);
    }
    __syncthreads();

    // ===================== phase 2: MLP rows [b*4, b*4+4) ====================
    if (t < 4) {
        int gi = b * 4 + t;
        float c0 = fmaxf(__ldcg(&g_acc[256 + gi]), 1.f);
        float c1 = fmaxf(__ldcg(&g_acc[320 + gi]), 1.f);
        float c2 = fmaxf(__ldcg(&g_acc[384 + gi]), 1.f);
        hg[t][0] = __ldcg(&g_acc[gi])       / c0;
        hg[t][1] = __ldcg(&g_acc[64  + gi]) / c1;
        hg[t][2] = __ldcg(&g_acc[128 + gi]) / c1;
        hg[t][3] = __ldcg(&g_acc[192 + gi]) / c2;
    }
    __syncthreads();                       // this block's g_acc reads done
    if (t == 0) s_r2 = atomicAdd(&g_ctr2, 1);

    // ---- layer 1: h1 = relu(hg @ Wc1 + bc1), 4 rows ----
    {
        int j    = t & (HID - 1);
        int half = t >> 7;
        float bb = sb1[j];
        float w0 = sWc1[j];
        float w1 = sWc1[HID + j];
        float w2 = sWc1[2 * HID + j];
        float w3 = sWc1[3 * HID + j];
#pragma unroll
        for (int rr = 0; rr < 2; rr++) {
            int r = half * 2 + rr;
            float a = bb + hg[r][0] * w0 + hg[r][1] * w1 + hg[r][2] * w2 + hg[r][3] * w3;
            h1s[r][j] = fmaxf(a, 0.f);
        }
    }

    // ---- layer 2: h2 = relu(h1 @ Wc2 + bc2), cooperative 32-row tiles ----
    {
        int col = t & (HID - 1);
        int rp  = t >> 7;                  // rows rp and rp+2
        float a0 = sb2[col], a1 = a0;
#pragma unroll
        for (int T = 0; T < 4; T++) {
            __syncthreads();
            const float4* W4 = (const float4*)(Wc2 + T * 32 * HID);
#pragma unroll
            for (int q = 0; q < 4; q++) {
                int fidx = q * TPB + t;    // 0..1023 float4s in tile
                float4 v = W4[fidx];
                *(float4*)&sW[fidx >> 5][(fidx & 31) * 4] = v;
            }
            __syncthreads();
#pragma unroll
            for (int kk = 0; kk < 32; kk++) {
                float w = sW[kk][col];
                a0 += h1s[rp][T * 32 + kk]     * w;
                a1 += h1s[rp + 2][T * 32 + kk] * w;
            }
        }
        h2s[rp][col]     = fmaxf(a0, 0.f);
        h2s[rp + 2][col] = fmaxf(a1, 0.f);
    }
    __syncthreads();

    // ---- layer 3: out = h2 @ Wc3 + bc3, 4x10, direct store ----
    if (t < 4 * NCLS) {
        int r = t / NCLS, c = t % NCLS;
        float acc = sb3[c];
#pragma unroll 8
        for (int k = 0; k < HID; k++)
            acc += h2s[r][k] * sWc3[k * NCLS + c];
        out[(b * 4 + r) * NCLS + c] = acc;
    }

    // ---- replay hygiene: last elected block resets global state ----
    __syncthreads();
    if (s_r2 == NMLP - 1) {                // all 16 blocks have read g_acc
        for (int i = t; i < 7 * BGRAPH; i += TPB) g_acc[i] = 0.f;
        if (t == 0) { g_ctr = 0; g_ctr2 = 0; }
    }
}

// ---------------------------------------------------------------------------
// launch: one fused kernel, one graph node
// ---------------------------------------------------------------------------
extern "C" void kernel_launch(void* const* d_in, const int* in_sizes, int n_in,
                              void* d_out, int out_size) {
    const float* h_comp = (const float*)d_in[0];
    const float* h_port = (const float*)d_in[1];
    const float* h_net  = (const float*)d_in[2];
    // d_in[3..6]: edge arrays — dead code in the reference, never read
    const int* gid_comp = (const int*)d_in[7];
    const int* gid_port = (const int*)d_in[8];
    const int* gid_net  = (const int*)d_in[9];
    // d_in[10..21]: GraphConv weights — dead code in the reference, never read
    const float* Wc1 = (const float*)d_in[22];
    const float* bc1 = (const float*)d_in[23];
    const float* Wc2 = (const float*)d_in[24];
    const float* bc2 = (const float*)d_in[25];
    const float* Wc3 = (const float*)d_in[26];
    const float* bc3 = (const float*)d_in[27];

    float* out = (float*)d_out;

    int nc = in_sizes[0];
    int np = in_sizes[1] / 2;
    int nn = in_sizes[2];

    int Bc = (nc + ELEMS_PER_BLOCK - 1) / ELEMS_PER_BLOCK;   // ~49
    int Bp = (np + ELEMS_PER_BLOCK - 1) / ELEMS_PER_BLOCK;   // ~196
    int Bn = (nn + ELEMS_PER_BLOCK - 1) / ELEMS_PER_BLOCK;   // ~74
    int grid = Bc + Bp + Bn;                                 // ~319 (>= NMLP)

    k_fused<<<grid, TPB>>>(h_comp, h_port, h_net,
                           gid_comp, gid_port, gid_net,
                           nc, np, nn, Bc, Bp,
                           Wc1, bc1, Wc2, bc2, Wc3, bc3,
                           out);
}